// round 2
// baseline (speedup 1.0000x reference)
#include <cuda_runtime.h>
#include <cuda_bf16.h>
#include <cstdint>

// ---------------------------------------------------------------------------
// LocalAttentionBlock: arsinh-norm -> NA2D(3x3, 8 heads) -> +res -> arsinh-norm
//                      -> MLP(256->512 gelu ->256) -> +res
// B=16, H=W=64, C=256, heads=8, hd=32
// ---------------------------------------------------------------------------

#define TOKENS   65536          // 16*64*64
#define C_DIM    256
#define QKV_DIM  768
#define FF_DIM   512
#define NHEADS   8
#define HDIM     32

// Scratch (device globals: allocation-free rule)
__device__ float g_h1  [(size_t)TOKENS * C_DIM];    // h1 then reused as h2
__device__ float g_qkv [(size_t)TOKENS * QKV_DIM];
__device__ float g_attn[(size_t)TOKENS * C_DIM];
__device__ float g_hmid[(size_t)TOKENS * C_DIM];
__device__ float g_ff  [(size_t)TOKENS * FF_DIM];

// ---------------------------------------------------------------------------
// Elementwise arsinh norm:  y = w[c] * asinh(x) + b[c]
// ---------------------------------------------------------------------------
__global__ void __launch_bounds__(256) arsinh_norm_kernel(
    const float* __restrict__ x, const float* __restrict__ w,
    const float* __restrict__ b, float* __restrict__ y, int n)
{
    int idx = blockIdx.x * 256 + threadIdx.x;
    if (idx < n) {
        int c = idx & (C_DIM - 1);
        y[idx] = fmaf(w[c], asinhf(x[idx]), b[c]);
    }
}

// ---------------------------------------------------------------------------
// SGEMM: C[M,N] = A[M,K] @ B[K,N] + bias[N]  (+ gelu) (+ res[M,N])
// Tiles: BM=BN=64, BK=16, 256 threads, 4x4 microtile. Dims divide tiles.
// ---------------------------------------------------------------------------
#define BM 64
#define BN 64
#define BK 16

__device__ __forceinline__ float gelu_exact(float v) {
    return 0.5f * v * (1.0f + erff(v * 0.70710678118654752440f));
}

template<bool GELU, bool RES>
__global__ void __launch_bounds__(256) sgemm_kernel(
    const float* __restrict__ A, const float* __restrict__ B,
    const float* __restrict__ bias, const float* __restrict__ res,
    float* __restrict__ C, int M, int N, int K)
{
    __shared__ float As[BK][BM + 4];   // +4 pad: keeps 16B alignment, cuts store conflicts
    __shared__ float Bs[BK][BN];

    const int bm = blockIdx.y * BM;
    const int bn = blockIdx.x * BN;
    const int tid = threadIdx.x;

    const int arow = tid >> 2;          // 0..63
    const int acol = (tid & 3) << 2;    // 0,4,8,12
    const int brow = tid >> 4;          // 0..15
    const int bcol = (tid & 15) << 2;   // 0..60
    const int tr   = tid >> 4;          // 0..15  (rows tr*4..tr*4+3)
    const int tc   = tid & 15;          // 0..15  (cols tc*4..tc*4+3)

    float acc[4][4];
    #pragma unroll
    for (int i = 0; i < 4; i++)
        #pragma unroll
        for (int j = 0; j < 4; j++) acc[i][j] = 0.0f;

    const float* Aptr = A + (size_t)(bm + arow) * K + acol;
    const float* Bptr = B + (size_t)brow * N + bn + bcol;

    for (int k0 = 0; k0 < K; k0 += BK) {
        float4 a = *(const float4*)(Aptr + k0);
        As[acol + 0][arow] = a.x;
        As[acol + 1][arow] = a.y;
        As[acol + 2][arow] = a.z;
        As[acol + 3][arow] = a.w;
        *(float4*)&Bs[brow][bcol] = *(const float4*)(Bptr + (size_t)k0 * N);
        __syncthreads();

        #pragma unroll
        for (int kk = 0; kk < BK; kk++) {
            float ra[4], rb[4];
            *(float4*)ra = *(const float4*)&As[kk][tr << 2];
            *(float4*)rb = *(const float4*)&Bs[kk][tc << 2];
            #pragma unroll
            for (int i = 0; i < 4; i++)
                #pragma unroll
                for (int j = 0; j < 4; j++)
                    acc[i][j] = fmaf(ra[i], rb[j], acc[i][j]);
        }
        __syncthreads();
    }

    // Epilogue
    float bs[4];
    *(float4*)bs = *(const float4*)&bias[bn + (tc << 2)];

    #pragma unroll
    for (int i = 0; i < 4; i++) {
        int row = bm + (tr << 2) + i;
        size_t off = (size_t)row * N + bn + (tc << 2);
        float v[4];
        #pragma unroll
        for (int j = 0; j < 4; j++) {
            v[j] = acc[i][j] + bs[j];
            if (GELU) v[j] = gelu_exact(v[j]);
        }
        if (RES) {
            float r[4];
            *(float4*)r = *(const float4*)&res[off];
            #pragma unroll
            for (int j = 0; j < 4; j++) v[j] += r[j];
        }
        *(float4*)&C[off] = *(const float4*)v;
    }
}

// ---------------------------------------------------------------------------
// NATTEN 3x3 neighborhood attention.
// One warp per (token, head); lane = head-dim index (hd=32).
// qkv layout per token: [0:256)=q, [256:512)=k, [512:768)=v, head-major inside.
// ---------------------------------------------------------------------------
__global__ void __launch_bounds__(256) natten_kernel(
    const float* __restrict__ qkv, float* __restrict__ out)
{
    int gwarp = (blockIdx.x * 256 + threadIdx.x) >> 5;
    int lane  = threadIdx.x & 31;
    int head  = gwarp & (NHEADS - 1);
    int token = gwarp >> 3;
    int b = token >> 12;
    int i = (token >> 6) & 63;
    int j = token & 63;

    const float scale = 0.17677669529663687f;  // 1/sqrt(32)
    float q = qkv[(size_t)token * QKV_DIM + head * HDIM + lane] * scale;

    int ri = min(max(i - 1, 0), 61);
    int ci = min(max(j - 1, 0), 61);

    float s[9], v[9];
    #pragma unroll
    for (int m = 0; m < 9; m++) {
        int ni = ri + m / 3;
        int nj = ci + m % 3;
        size_t nt = ((size_t)((b << 6) + ni) * 64 + nj) * QKV_DIM + head * HDIM + lane;
        float kk = qkv[nt + 256];
        v[m]     = qkv[nt + 512];
        float p = q * kk;
        #pragma unroll
        for (int o = 16; o > 0; o >>= 1)
            p += __shfl_xor_sync(0xffffffffu, p, o);
        s[m] = p;   // every lane holds the full dot product
    }

    float mx = s[0];
    #pragma unroll
    for (int m = 1; m < 9; m++) mx = fmaxf(mx, s[m]);
    float sum = 0.0f;
    #pragma unroll
    for (int m = 0; m < 9; m++) { s[m] = __expf(s[m] - mx); sum += s[m]; }
    float inv = 1.0f / sum;
    float o = 0.0f;
    #pragma unroll
    for (int m = 0; m < 9; m++) o = fmaf(s[m], v[m], o);

    out[(size_t)token * C_DIM + head * HDIM + lane] = o * inv;
}

// ---------------------------------------------------------------------------
// Launcher
// ---------------------------------------------------------------------------
extern "C" void kernel_launch(void* const* d_in, const int* in_sizes, int n_in,
                              void* d_out, int out_size)
{
    (void)in_sizes; (void)n_in; (void)out_size;
    const float* h      = (const float*)d_in[0];
    const float* qkv_w  = (const float*)d_in[1];
    const float* qkv_b  = (const float*)d_in[2];
    const float* proj_w = (const float*)d_in[3];
    const float* proj_b = (const float*)d_in[4];
    const float* n1_w   = (const float*)d_in[5];
    const float* n1_b   = (const float*)d_in[6];
    const float* n2_w   = (const float*)d_in[7];
    const float* n2_b   = (const float*)d_in[8];
    const float* mlp_w1 = (const float*)d_in[9];
    const float* mlp_b1 = (const float*)d_in[10];
    const float* mlp_w2 = (const float*)d_in[11];
    const float* mlp_b2 = (const float*)d_in[12];
    float* out = (float*)d_out;

    float *h1, *qkv, *attn, *hmid, *ff;
    cudaGetSymbolAddress((void**)&h1,   g_h1);
    cudaGetSymbolAddress((void**)&qkv,  g_qkv);
    cudaGetSymbolAddress((void**)&attn, g_attn);
    cudaGetSymbolAddress((void**)&hmid, g_hmid);
    cudaGetSymbolAddress((void**)&ff,   g_ff);

    const int M = TOKENS;
    const int nElem = TOKENS * C_DIM;

    // 1. h1 = arsinh_norm(h; n1)
    arsinh_norm_kernel<<<(nElem + 255) / 256, 256>>>(h, n1_w, n1_b, h1, nElem);

    // 2. qkv = h1 @ qkv_w + qkv_b
    {
        dim3 grid(QKV_DIM / BN, M / BM);
        sgemm_kernel<false, false><<<grid, 256>>>(h1, qkv_w, qkv_b, nullptr, qkv,
                                                  M, QKV_DIM, C_DIM);
    }

    // 3. NATTEN attention
    natten_kernel<<<(TOKENS * NHEADS) / 8, 256>>>(qkv, attn);

    // 4. hmid = h + attn @ proj_w + proj_b
    {
        dim3 grid(C_DIM / BN, M / BM);
        sgemm_kernel<false, true><<<grid, 256>>>(attn, proj_w, proj_b, h, hmid,
                                                 M, C_DIM, C_DIM);
    }

    // 5. h2 = arsinh_norm(hmid; n2)   (reuse g_h1)
    arsinh_norm_kernel<<<(nElem + 255) / 256, 256>>>(hmid, n2_w, n2_b, h1, nElem);

    // 6. ff = gelu(h2 @ mlp_w1 + mlp_b1)
    {
        dim3 grid(FF_DIM / BN, M / BM);
        sgemm_kernel<true, false><<<grid, 256>>>(h1, mlp_w1, mlp_b1, nullptr, ff,
                                                 M, FF_DIM, C_DIM);
    }

    // 7. out = hmid + ff @ mlp_w2 + mlp_b2
    {
        dim3 grid(C_DIM / BN, M / BM);
        sgemm_kernel<false, true><<<grid, 256>>>(ff, mlp_w2, mlp_b2, hmid, out,
                                                 M, C_DIM, FF_DIM);
    }
}

// round 6
// speedup vs baseline: 2.6326x; 2.6326x over previous
#include <cuda_runtime.h>
#include <cuda_bf16.h>
#include <cstdint>

// ---------------------------------------------------------------------------
// LocalAttentionBlock on GB300 (base sm_103 target -> mma.sync tf32 HMMA).
// B=16, H=W=64, C=256, heads=8, hd=32
// ---------------------------------------------------------------------------

#define TOKENS   65536
#define C_DIM    256
#define QKV_DIM  768
#define FF_DIM   512
#define NHEADS   8
#define HDIM     32

// Scratch (device globals — allocation-free rule)
__device__ float g_h1  [(size_t)TOKENS * C_DIM];
__device__ float g_qkv [(size_t)TOKENS * QKV_DIM];
__device__ float g_attn[(size_t)TOKENS * C_DIM];
__device__ float g_hmid[(size_t)TOKENS * C_DIM];
__device__ float g_ff  [(size_t)TOKENS * FF_DIM];
// Transposed ([N,K] K-major, tf32-rounded) weights
__device__ float g_qkvt [(size_t)QKV_DIM * C_DIM];
__device__ float g_projt[(size_t)C_DIM * C_DIM];
__device__ float g_mlp1t[(size_t)FF_DIM * C_DIM];
__device__ float g_mlp2t[(size_t)C_DIM * FF_DIM];

// ---------------------------------------------------------------------------
// Helpers
// ---------------------------------------------------------------------------
__device__ __forceinline__ uint32_t smem_u32(const void* p) {
    uint32_t a;
    asm("{ .reg .u64 t; cvta.to.shared.u64 t, %1; cvt.u32.u64 %0, t; }"
        : "=r"(a) : "l"(p));
    return a;
}
__device__ __forceinline__ float rtf32(float x) {
    float y;
    asm("cvt.rna.tf32.f32 %0, %1;" : "=f"(y) : "f"(x));
    return y;
}
__device__ __forceinline__ uint32_t lds32(uint32_t a) {
    uint32_t v;
    asm volatile("ld.shared.b32 %0, [%1];" : "=r"(v) : "r"(a));
    return v;
}
#define CP_ASYNC16(dst, src) \
    asm volatile("cp.async.cg.shared.global [%0], [%1], 16;" :: "r"(dst), "l"(src))
#define CP_COMMIT() asm volatile("cp.async.commit_group;" ::: "memory")
#define CP_WAIT0()  asm volatile("cp.async.wait_group 0;" ::: "memory")

#define MMA_TF32(cf, av, bv) \
    asm volatile("mma.sync.aligned.m16n8k8.row.col.f32.tf32.tf32.f32 " \
        "{%0,%1,%2,%3}, {%4,%5,%6,%7}, {%8,%9}, {%0,%1,%2,%3};" \
        : "+f"((cf)[0]), "+f"((cf)[1]), "+f"((cf)[2]), "+f"((cf)[3]) \
        : "r"((av)[0]), "r"((av)[1]), "r"((av)[2]), "r"((av)[3]), \
          "r"((bv)[0]), "r"((bv)[1]))

__device__ __forceinline__ float gelu_exact(float v) {
    return 0.5f * v * (1.0f + erff(v * 0.70710678118654752440f));
}

// ---------------------------------------------------------------------------
// Elementwise arsinh norm: y = round_tf32(w[c]*asinh(x)+b[c])
// ---------------------------------------------------------------------------
__global__ void __launch_bounds__(256) arsinh_norm_kernel(
    const float* __restrict__ x, const float* __restrict__ w,
    const float* __restrict__ b, float* __restrict__ y, int n)
{
    int idx = blockIdx.x * 256 + threadIdx.x;
    if (idx < n) {
        int c = idx & (C_DIM - 1);
        y[idx] = rtf32(fmaf(w[c], asinhf(x[idx]), b[c]));
    }
}

// ---------------------------------------------------------------------------
// Transpose W[K,N] -> Wt[N,K] with tf32 rounding
// ---------------------------------------------------------------------------
__global__ void __launch_bounds__(256) transpose_kernel(
    const float* __restrict__ in, float* __restrict__ out, int K, int N)
{
    __shared__ float t[32][33];
    int n0 = blockIdx.x * 32, k0 = blockIdx.y * 32;
    int tx = threadIdx.x & 31, ty = threadIdx.x >> 5;  // 32 x 8
    #pragma unroll
    for (int i = 0; i < 4; i++)
        t[ty + i * 8][tx] = in[(size_t)(k0 + ty + i * 8) * N + n0 + tx];
    __syncthreads();
    #pragma unroll
    for (int i = 0; i < 4; i++)
        out[(size_t)(n0 + ty + i * 8) * K + k0 + tx] = rtf32(t[tx][ty + i * 8]);
}

// ---------------------------------------------------------------------------
// tf32 mma.sync GEMM: C[M,N] = A[M,K] @ Bt[N,K]^T + bias (+gelu)(+res)(+round)
// CTA 128x128x32, 256 thr, 8 warps x (32x64). cp.async double-buffered smem.
// Smem layout XOR-swizzled: elem(row,col) at row*32 + (((col>>2)^row)&7)*4 + (col&3)
// ---------------------------------------------------------------------------
#define BM 128
#define BN 128
#define BK 32
#define STAGE_BYTES (BM * BK * 4)   // 16 KB per tile

template<bool GELU, bool RES, bool ROUND>
__global__ void __launch_bounds__(256, 2)
gemm_mma_kernel(const float* __restrict__ A, const float* __restrict__ Bt,
                const float* __restrict__ bias, const float* __restrict__ res,
                float* __restrict__ C, int M, int N, int K)
{
    extern __shared__ float smp[];          // [2][4096] A, [2][4096] B = 64 KB
    const uint32_t as_base = smem_u32(smp);
    const uint32_t bs_base = as_base + 2 * STAGE_BYTES;

    const int tid  = threadIdx.x;
    const int wid  = tid >> 5;
    const int lane = tid & 31;
    const int g    = lane >> 2;             // 0..7
    const int tig  = lane & 3;              // 0..3
    const int wm   = wid >> 1;              // 0..3  -> rows wm*32
    const int wn   = wid & 1;               // 0..1  -> cols wn*64
    const int bm   = blockIdx.y * BM;
    const int bn   = blockIdx.x * BN;

    const int lrow = tid >> 3;              // 0..31 (+32 per chunk)
    const int lcg  = tid & 7;               // float4 column group

    float c[2][8][4];
    #pragma unroll
    for (int mt = 0; mt < 2; mt++)
        #pragma unroll
        for (int nt = 0; nt < 8; nt++)
            #pragma unroll
            for (int u = 0; u < 4; u++) c[mt][nt][u] = 0.0f;

    // stage loader: 8 cp.async(16B) per thread
    auto load_stage = [&](int buf, int k0) {
        const uint32_t ab = as_base + buf * STAGE_BYTES;
        const uint32_t bb = bs_base + buf * STAGE_BYTES;
        #pragma unroll
        for (int i = 0; i < 4; i++) {
            const int row = lrow + i * 32;
            const int sw  = ((lcg ^ row) & 7) << 2;
            const uint32_t soff = (uint32_t)(row * 32 + sw) * 4;
            CP_ASYNC16(ab + soff, A  + (size_t)(bm + row) * K + k0 + lcg * 4);
            CP_ASYNC16(bb + soff, Bt + (size_t)(bn + row) * K + k0 + lcg * 4);
        }
    };

    load_stage(0, 0);
    CP_COMMIT();

    const int S = K / BK;
    for (int s = 0; s < S; s++) {
        CP_WAIT0();
        __syncthreads();
        if (s + 1 < S) { load_stage((s + 1) & 1, (s + 1) * BK); CP_COMMIT(); }

        const uint32_t ab = as_base + (s & 1) * STAGE_BYTES;
        const uint32_t bb = bs_base + (s & 1) * STAGE_BYTES;

        #pragma unroll
        for (int kk = 0; kk < 4; kk++) {
            const int cg0 = kk * 2;         // col groups cg0, cg0+1  (k = kk*8 ..)
            uint32_t a[2][4], b[8][2];
            #pragma unroll
            for (int mt = 0; mt < 2; mt++) {
                const int r0 = wm * 32 + mt * 16 + g;
                const int r1 = r0 + 8;
                a[mt][0] = lds32(ab + (uint32_t)(r0 * 32 + ((cg0 ^ r0) & 7) * 4 + tig) * 4);
                a[mt][1] = lds32(ab + (uint32_t)(r1 * 32 + ((cg0 ^ r1) & 7) * 4 + tig) * 4);
                a[mt][2] = lds32(ab + (uint32_t)(r0 * 32 + (((cg0 + 1) ^ r0) & 7) * 4 + tig) * 4);
                a[mt][3] = lds32(ab + (uint32_t)(r1 * 32 + (((cg0 + 1) ^ r1) & 7) * 4 + tig) * 4);
            }
            #pragma unroll
            for (int nt = 0; nt < 8; nt++) {
                const int rn = wn * 64 + nt * 8 + g;
                b[nt][0] = lds32(bb + (uint32_t)(rn * 32 + ((cg0 ^ rn) & 7) * 4 + tig) * 4);
                b[nt][1] = lds32(bb + (uint32_t)(rn * 32 + (((cg0 + 1) ^ rn) & 7) * 4 + tig) * 4);
            }
            #pragma unroll
            for (int mt = 0; mt < 2; mt++)
                #pragma unroll
                for (int nt = 0; nt < 8; nt++)
                    MMA_TF32(c[mt][nt], a[mt], b[nt]);
        }
        __syncthreads();
    }

    // Epilogue
    #pragma unroll
    for (int mt = 0; mt < 2; mt++) {
        #pragma unroll
        for (int half = 0; half < 2; half++) {
            const int row = bm + wm * 32 + mt * 16 + g + half * 8;
            #pragma unroll
            for (int nt = 0; nt < 8; nt++) {
                const int col = bn + wn * 64 + nt * 8 + tig * 2;
                float v0 = c[mt][nt][half * 2 + 0] + bias[col];
                float v1 = c[mt][nt][half * 2 + 1] + bias[col + 1];
                if (GELU) { v0 = gelu_exact(v0); v1 = gelu_exact(v1); }
                if (RES) {
                    float2 r = *(const float2*)(res + (size_t)row * N + col);
                    v0 += r.x; v1 += r.y;
                }
                if (ROUND) { v0 = rtf32(v0); v1 = rtf32(v1); }
                *(float2*)(C + (size_t)row * N + col) = make_float2(v0, v1);
            }
        }
    }
}

// ---------------------------------------------------------------------------
// NATTEN 3x3: one warp per (token, head); lane = head-dim. Output tf32-rounded.
// ---------------------------------------------------------------------------
__global__ void __launch_bounds__(256) natten_kernel(
    const float* __restrict__ qkv, float* __restrict__ out)
{
    int gwarp = (blockIdx.x * 256 + threadIdx.x) >> 5;
    int lane  = threadIdx.x & 31;
    int head  = gwarp & (NHEADS - 1);
    int token = gwarp >> 3;
    int b = token >> 12;
    int i = (token >> 6) & 63;
    int j = token & 63;

    const float scale = 0.17677669529663687f;  // 1/sqrt(32)
    float q = qkv[(size_t)token * QKV_DIM + head * HDIM + lane] * scale;

    int ri = min(max(i - 1, 0), 61);
    int ci = min(max(j - 1, 0), 61);

    float s[9], v[9];
    #pragma unroll
    for (int m = 0; m < 9; m++) {
        int ni = ri + m / 3;
        int nj = ci + m % 3;
        size_t nt = ((size_t)((b << 6) + ni) * 64 + nj) * QKV_DIM + head * HDIM + lane;
        float kk = qkv[nt + 256];
        v[m]     = qkv[nt + 512];
        float p = q * kk;
        #pragma unroll
        for (int o = 16; o > 0; o >>= 1)
            p += __shfl_xor_sync(0xffffffffu, p, o);
        s[m] = p;
    }

    float mx = s[0];
    #pragma unroll
    for (int m = 1; m < 9; m++) mx = fmaxf(mx, s[m]);
    float sum = 0.0f;
    #pragma unroll
    for (int m = 0; m < 9; m++) { s[m] = __expf(s[m] - mx); sum += s[m]; }
    float inv = 1.0f / sum;
    float o = 0.0f;
    #pragma unroll
    for (int m = 0; m < 9; m++) o = fmaf(s[m], v[m], o);

    out[(size_t)token * C_DIM + head * HDIM + lane] = rtf32(o * inv);
}

// ---------------------------------------------------------------------------
// Launcher
// ---------------------------------------------------------------------------
#define GEMM_SMEM (4 * STAGE_BYTES)   // 64 KB

extern "C" void kernel_launch(void* const* d_in, const int* in_sizes, int n_in,
                              void* d_out, int out_size)
{
    (void)in_sizes; (void)n_in; (void)out_size;
    const float* h      = (const float*)d_in[0];
    const float* qkv_w  = (const float*)d_in[1];
    const float* qkv_b  = (const float*)d_in[2];
    const float* proj_w = (const float*)d_in[3];
    const float* proj_b = (const float*)d_in[4];
    const float* n1_w   = (const float*)d_in[5];
    const float* n1_b   = (const float*)d_in[6];
    const float* n2_w   = (const float*)d_in[7];
    const float* n2_b   = (const float*)d_in[8];
    const float* mlp_w1 = (const float*)d_in[9];
    const float* mlp_b1 = (const float*)d_in[10];
    const float* mlp_w2 = (const float*)d_in[11];
    const float* mlp_b2 = (const float*)d_in[12];
    float* out = (float*)d_out;

    float *h1, *qkv, *attn, *hmid, *ff, *qkvt, *projt, *mlp1t, *mlp2t;
    cudaGetSymbolAddress((void**)&h1,    g_h1);
    cudaGetSymbolAddress((void**)&qkv,   g_qkv);
    cudaGetSymbolAddress((void**)&attn,  g_attn);
    cudaGetSymbolAddress((void**)&hmid,  g_hmid);
    cudaGetSymbolAddress((void**)&ff,    g_ff);
    cudaGetSymbolAddress((void**)&qkvt,  g_qkvt);
    cudaGetSymbolAddress((void**)&projt, g_projt);
    cudaGetSymbolAddress((void**)&mlp1t, g_mlp1t);
    cudaGetSymbolAddress((void**)&mlp2t, g_mlp2t);

    // Allow 64 KB dynamic smem (idempotent, host-side setting; not stream work)
    cudaFuncSetAttribute(gemm_mma_kernel<false, false, false>,
                         cudaFuncAttributeMaxDynamicSharedMemorySize, GEMM_SMEM);
    cudaFuncSetAttribute(gemm_mma_kernel<false, true, false>,
                         cudaFuncAttributeMaxDynamicSharedMemorySize, GEMM_SMEM);
    cudaFuncSetAttribute(gemm_mma_kernel<true, false, true>,
                         cudaFuncAttributeMaxDynamicSharedMemorySize, GEMM_SMEM);

    const int M = TOKENS;
    const int nElem = TOKENS * C_DIM;

    // Weight transposes (tf32-rounded), cheap
    transpose_kernel<<<dim3(QKV_DIM / 32, C_DIM / 32), 256>>>(qkv_w,  qkvt,  C_DIM, QKV_DIM);
    transpose_kernel<<<dim3(C_DIM / 32, C_DIM / 32),   256>>>(proj_w, projt, C_DIM, C_DIM);
    transpose_kernel<<<dim3(FF_DIM / 32, C_DIM / 32),  256>>>(mlp_w1, mlp1t, C_DIM, FF_DIM);
    transpose_kernel<<<dim3(C_DIM / 32, FF_DIM / 32),  256>>>(mlp_w2, mlp2t, FF_DIM, C_DIM);

    // 1. h1 = round_tf32(arsinh_norm(h; n1))
    arsinh_norm_kernel<<<(nElem + 255) / 256, 256>>>(h, n1_w, n1_b, h1, nElem);

    // 2. qkv = h1 @ qkv_w + qkv_b
    gemm_mma_kernel<false, false, false><<<dim3(QKV_DIM / BN, M / BM), 256, GEMM_SMEM>>>(
        h1, qkvt, qkv_b, nullptr, qkv, M, QKV_DIM, C_DIM);

    // 3. NATTEN attention (tf32-rounded output)
    natten_kernel<<<(TOKENS * NHEADS) / 8, 256>>>(qkv, attn);

    // 4. hmid = h + attn @ proj_w + proj_b
    gemm_mma_kernel<false, true, false><<<dim3(C_DIM / BN, M / BM), 256, GEMM_SMEM>>>(
        attn, projt, proj_b, h, hmid, M, C_DIM, C_DIM);

    // 5. h2 = round_tf32(arsinh_norm(hmid; n2))   (reuse g_h1)
    arsinh_norm_kernel<<<(nElem + 255) / 256, 256>>>(hmid, n2_w, n2_b, h1, nElem);

    // 6. ff = round_tf32(gelu(h2 @ mlp_w1 + mlp_b1))
    gemm_mma_kernel<true, false, true><<<dim3(FF_DIM / BN, M / BM), 256, GEMM_SMEM>>>(
        h1, mlp1t, mlp_b1, nullptr, ff, M, FF_DIM, C_DIM);

    // 7. out = hmid + ff @ mlp_w2 + mlp_b2
    gemm_mma_kernel<false, true, false><<<dim3(C_DIM / BN, M / BM), 256, GEMM_SMEM>>>(
        ff, mlp2t, mlp_b2, hmid, out, M, C_DIM, FF_DIM);
}

// round 8
// speedup vs baseline: 3.6757x; 1.3962x over previous
#include <cuda_runtime.h>
#include <cuda_bf16.h>
#include <cstdint>

// ---------------------------------------------------------------------------
// LocalAttentionBlock on GB300 (base sm_103 target): bf16 mma.sync m16n8k16
// GEMMs with ldmatrix fragments + fp32 NATTEN.
// B=16, H=W=64, C=256, heads=8, hd=32
// ---------------------------------------------------------------------------

#define TOKENS   65536
#define C_DIM    256
#define QKV_DIM  768
#define FF_DIM   512
#define NHEADS   8
#define HDIM     32

// Scratch (device globals — allocation-free rule)
__device__ __nv_bfloat16 g_h1  [(size_t)TOKENS * C_DIM];   // h1 then h2
__device__ float         g_qkv [(size_t)TOKENS * QKV_DIM]; // fp32 (natten input)
__device__ __nv_bfloat16 g_attn[(size_t)TOKENS * C_DIM];
__device__ float         g_hmid[(size_t)TOKENS * C_DIM];
__device__ __nv_bfloat16 g_ff  [(size_t)TOKENS * FF_DIM];
// Transposed ([N,K] K-major, bf16) weights
__device__ __nv_bfloat16 g_qkvt [(size_t)QKV_DIM * C_DIM];
__device__ __nv_bfloat16 g_projt[(size_t)C_DIM * C_DIM];
__device__ __nv_bfloat16 g_mlp1t[(size_t)FF_DIM * C_DIM];
__device__ __nv_bfloat16 g_mlp2t[(size_t)C_DIM * FF_DIM];

// ---------------------------------------------------------------------------
// Helpers
// ---------------------------------------------------------------------------
__device__ __forceinline__ uint32_t smem_u32(const void* p) {
    uint32_t a;
    asm("{ .reg .u64 t; cvta.to.shared.u64 t, %1; cvt.u32.u64 %0, t; }"
        : "=r"(a) : "l"(p));
    return a;
}
#define CP_ASYNC16(dst, src) \
    asm volatile("cp.async.cg.shared.global [%0], [%1], 16;" :: "r"(dst), "l"(src))
#define CP_COMMIT() asm volatile("cp.async.commit_group;" ::: "memory")
#define CP_WAIT0()  asm volatile("cp.async.wait_group 0;" ::: "memory")

#define LDSM_X4(r0, r1, r2, r3, addr) \
    asm volatile("ldmatrix.sync.aligned.m8n8.x4.shared.b16 {%0,%1,%2,%3}, [%4];" \
        : "=r"(r0), "=r"(r1), "=r"(r2), "=r"(r3) : "r"(addr))

#define MMA_BF16(cf, av, bv) \
    asm volatile("mma.sync.aligned.m16n8k16.row.col.f32.bf16.bf16.f32 " \
        "{%0,%1,%2,%3}, {%4,%5,%6,%7}, {%8,%9}, {%0,%1,%2,%3};" \
        : "+f"((cf)[0]), "+f"((cf)[1]), "+f"((cf)[2]), "+f"((cf)[3]) \
        : "r"((av)[0]), "r"((av)[1]), "r"((av)[2]), "r"((av)[3]), \
          "r"((bv)[0]), "r"((bv)[1]))

__device__ __forceinline__ float gelu_exact(float v) {
    return 0.5f * v * (1.0f + erff(v * 0.70710678118654752440f));
}

// ---------------------------------------------------------------------------
// Elementwise arsinh norm: y = bf16(w[c]*asinh(x)+b[c])
// ---------------------------------------------------------------------------
__global__ void __launch_bounds__(256) arsinh_norm_kernel(
    const float* __restrict__ x, const float* __restrict__ w,
    const float* __restrict__ b, __nv_bfloat16* __restrict__ y, int n)
{
    int idx = blockIdx.x * 256 + threadIdx.x;
    if (idx < n) {
        int c = idx & (C_DIM - 1);
        y[idx] = __float2bfloat16_rn(fmaf(w[c], asinhf(x[idx]), b[c]));
    }
}

// ---------------------------------------------------------------------------
// Transpose W[K,N] -> Wt[N,K] bf16
// ---------------------------------------------------------------------------
__global__ void __launch_bounds__(256) transpose_kernel(
    const float* __restrict__ in, __nv_bfloat16* __restrict__ out, int K, int N)
{
    __shared__ float t[32][33];
    int n0 = blockIdx.x * 32, k0 = blockIdx.y * 32;
    int tx = threadIdx.x & 31, ty = threadIdx.x >> 5;  // 32 x 8
    #pragma unroll
    for (int i = 0; i < 4; i++)
        t[ty + i * 8][tx] = in[(size_t)(k0 + ty + i * 8) * N + n0 + tx];
    __syncthreads();
    #pragma unroll
    for (int i = 0; i < 4; i++)
        out[(size_t)(n0 + ty + i * 8) * K + k0 + tx] =
            __float2bfloat16_rn(t[tx][ty + i * 8]);
}

// ---------------------------------------------------------------------------
// bf16 mma.sync GEMM: C[M,N] = A[M,K] @ Bt[N,K]^T + bias (+gelu)(+res)
// CTA 128x128, BK=64 (128B rows, XOR-swizzled chunks), double-buffered
// cp.async, ldmatrix.x4 fragment loads, 8 warps x (32m x 64n).
// ---------------------------------------------------------------------------
#define BM 128
#define BN 128
#define BKE 64                        // K elements per stage
#define STG (BM * BKE * 2)            // 16 KB per tile

template<bool GELU, bool RES, bool OUTBF16>
__global__ void __launch_bounds__(256, 2)
gemm_bf16_kernel(const __nv_bfloat16* __restrict__ A,
                 const __nv_bfloat16* __restrict__ Bt,
                 const float* __restrict__ bias, const float* __restrict__ res,
                 void* __restrict__ Cout, int M, int N, int K)
{
    extern __shared__ char smp[];     // [2]A + [2]B = 64 KB
    const uint32_t as_base = smem_u32(smp);
    const uint32_t bs_base = as_base + 2 * STG;

    const int tid  = threadIdx.x;
    const int wid  = tid >> 5;
    const int lane = tid & 31;
    const int g    = lane >> 2;
    const int tig  = lane & 3;
    const int wm   = wid >> 1;        // rows wm*32
    const int wn   = wid & 1;         // cols wn*64
    const int bm   = blockIdx.y * BM;
    const int bn   = blockIdx.x * BN;

    // ldmatrix per-lane row/chunk decomposition
    const int ar  = (lane & 7) + ((lane >> 3) & 1) * 8;  // A row within 16
    const int acb = lane >> 4;                           // A chunk bit
    const int br  = (lane & 7) + ((lane >> 4) & 1) * 8;  // B row within 16
    const int bcb = (lane >> 3) & 1;                     // B chunk bit

    float c[2][8][4];
    #pragma unroll
    for (int mt = 0; mt < 2; mt++)
        #pragma unroll
        for (int nt = 0; nt < 8; nt++)
            #pragma unroll
            for (int u = 0; u < 4; u++) c[mt][nt][u] = 0.0f;

    // Stage loader: 1024 16B chunks per tile, 4 per thread per tile.
    auto load_stage = [&](int buf, int k0) {
        const uint32_t ab = as_base + buf * STG;
        const uint32_t bb = bs_base + buf * STG;
        #pragma unroll
        for (int i = 0; i < 4; i++) {
            const int id = tid + i * 256;
            const int r = id >> 3, ch = id & 7;
            const uint32_t off = (uint32_t)(r * 128 + ((ch ^ (r & 7)) << 4));
            CP_ASYNC16(ab + off, A  + (size_t)(bm + r) * K + k0 + ch * 8);
            CP_ASYNC16(bb + off, Bt + (size_t)(bn + r) * K + k0 + ch * 8);
        }
    };

    load_stage(0, 0);
    CP_COMMIT();

    const int S = K / BKE;
    for (int s = 0; s < S; s++) {
        CP_WAIT0();
        __syncthreads();
        if (s + 1 < S) { load_stage((s + 1) & 1, (s + 1) * BKE); CP_COMMIT(); }

        const uint32_t ab = as_base + (s & 1) * STG;
        const uint32_t bb = bs_base + (s & 1) * STG;

        #pragma unroll
        for (int kk = 0; kk < 4; kk++) {         // 4 x k16
            uint32_t a[2][4], b[8][2];
            #pragma unroll
            for (int mt = 0; mt < 2; mt++) {
                const int row = wm * 32 + mt * 16 + ar;
                const uint32_t ad = ab + row * 128
                    + (((2 * kk + acb) ^ (row & 7)) << 4);
                LDSM_X4(a[mt][0], a[mt][1], a[mt][2], a[mt][3], ad);
            }
            #pragma unroll
            for (int p = 0; p < 4; p++) {
                const int row = wn * 64 + p * 16 + br;
                const uint32_t bd = bb + row * 128
                    + (((2 * kk + bcb) ^ (row & 7)) << 4);
                LDSM_X4(b[2 * p][0], b[2 * p][1], b[2 * p + 1][0], b[2 * p + 1][1], bd);
            }
            #pragma unroll
            for (int mt = 0; mt < 2; mt++)
                #pragma unroll
                for (int nt = 0; nt < 8; nt++)
                    MMA_BF16(c[mt][nt], a[mt], b[nt]);
        }
        __syncthreads();
    }

    // Epilogue
    #pragma unroll
    for (int mt = 0; mt < 2; mt++) {
        #pragma unroll
        for (int half = 0; half < 2; half++) {
            const int row = bm + wm * 32 + mt * 16 + g + half * 8;
            #pragma unroll
            for (int nt = 0; nt < 8; nt++) {
                const int col = bn + wn * 64 + nt * 8 + tig * 2;
                float v0 = c[mt][nt][half * 2 + 0] + bias[col];
                float v1 = c[mt][nt][half * 2 + 1] + bias[col + 1];
                if (GELU) { v0 = gelu_exact(v0); v1 = gelu_exact(v1); }
                if (RES) {
                    float2 r = *(const float2*)(res + (size_t)row * N + col);
                    v0 += r.x; v1 += r.y;
                }
                if (OUTBF16) {
                    *(__nv_bfloat162*)((__nv_bfloat16*)Cout + (size_t)row * N + col)
                        = __floats2bfloat162_rn(v0, v1);
                } else {
                    *(float2*)((float*)Cout + (size_t)row * N + col)
                        = make_float2(v0, v1);
                }
            }
        }
    }
}

// ---------------------------------------------------------------------------
// NATTEN 3x3: one warp per (token, head); lane = head-dim. Output bf16.
// ---------------------------------------------------------------------------
__global__ void __launch_bounds__(256) natten_kernel(
    const float* __restrict__ qkv, __nv_bfloat16* __restrict__ out)
{
    int gwarp = (blockIdx.x * 256 + threadIdx.x) >> 5;
    int lane  = threadIdx.x & 31;
    int head  = gwarp & (NHEADS - 1);
    int token = gwarp >> 3;
    int b = token >> 12;
    int i = (token >> 6) & 63;
    int j = token & 63;

    const float scale = 0.17677669529663687f;  // 1/sqrt(32)
    float q = qkv[(size_t)token * QKV_DIM + head * HDIM + lane] * scale;

    int ri = min(max(i - 1, 0), 61);
    int ci = min(max(j - 1, 0), 61);

    float s[9], v[9];
    #pragma unroll
    for (int m = 0; m < 9; m++) {
        int ni = ri + m / 3;
        int nj = ci + m % 3;
        size_t nt = ((size_t)((b << 6) + ni) * 64 + nj) * QKV_DIM + head * HDIM + lane;
        float kk = qkv[nt + 256];
        v[m]     = qkv[nt + 512];
        float p = q * kk;
        #pragma unroll
        for (int o = 16; o > 0; o >>= 1)
            p += __shfl_xor_sync(0xffffffffu, p, o);
        s[m] = p;
    }

    float mx = s[0];
    #pragma unroll
    for (int m = 1; m < 9; m++) mx = fmaxf(mx, s[m]);
    float sum = 0.0f;
    #pragma unroll
    for (int m = 0; m < 9; m++) { s[m] = __expf(s[m] - mx); sum += s[m]; }
    float inv = 1.0f / sum;
    float o = 0.0f;
    #pragma unroll
    for (int m = 0; m < 9; m++) o = fmaf(s[m], v[m], o);

    out[(size_t)token * C_DIM + head * HDIM + lane] = __float2bfloat16_rn(o * inv);
}

// ---------------------------------------------------------------------------
// Launcher
// ---------------------------------------------------------------------------
#define GEMM_SMEM (4 * STG)   // 64 KB

extern "C" void kernel_launch(void* const* d_in, const int* in_sizes, int n_in,
                              void* d_out, int out_size)
{
    (void)in_sizes; (void)n_in; (void)out_size;
    const float* h      = (const float*)d_in[0];
    const float* qkv_w  = (const float*)d_in[1];
    const float* qkv_b  = (const float*)d_in[2];
    const float* proj_w = (const float*)d_in[3];
    const float* proj_b = (const float*)d_in[4];
    const float* n1_w   = (const float*)d_in[5];
    const float* n1_b   = (const float*)d_in[6];
    const float* n2_w   = (const float*)d_in[7];
    const float* n2_b   = (const float*)d_in[8];
    const float* mlp_w1 = (const float*)d_in[9];
    const float* mlp_b1 = (const float*)d_in[10];
    const float* mlp_w2 = (const float*)d_in[11];
    const float* mlp_b2 = (const float*)d_in[12];
    float* out = (float*)d_out;

    __nv_bfloat16 *h1, *attn, *ff, *qkvt, *projt, *mlp1t, *mlp2t;
    float *qkv, *hmid;
    cudaGetSymbolAddress((void**)&h1,    g_h1);
    cudaGetSymbolAddress((void**)&qkv,   g_qkv);
    cudaGetSymbolAddress((void**)&attn,  g_attn);
    cudaGetSymbolAddress((void**)&hmid,  g_hmid);
    cudaGetSymbolAddress((void**)&ff,    g_ff);
    cudaGetSymbolAddress((void**)&qkvt,  g_qkvt);
    cudaGetSymbolAddress((void**)&projt, g_projt);
    cudaGetSymbolAddress((void**)&mlp1t, g_mlp1t);
    cudaGetSymbolAddress((void**)&mlp2t, g_mlp2t);

    cudaFuncSetAttribute(gemm_bf16_kernel<false, false, false>,
                         cudaFuncAttributeMaxDynamicSharedMemorySize, GEMM_SMEM);
    cudaFuncSetAttribute(gemm_bf16_kernel<false, true, false>,
                         cudaFuncAttributeMaxDynamicSharedMemorySize, GEMM_SMEM);
    cudaFuncSetAttribute(gemm_bf16_kernel<true, false, true>,
                         cudaFuncAttributeMaxDynamicSharedMemorySize, GEMM_SMEM);

    const int M = TOKENS;
    const int nElem = TOKENS * C_DIM;

    // Weight transposes (bf16), cheap
    transpose_kernel<<<dim3(QKV_DIM / 32, C_DIM / 32), 256>>>(qkv_w,  qkvt,  C_DIM, QKV_DIM);
    transpose_kernel<<<dim3(C_DIM / 32, C_DIM / 32),   256>>>(proj_w, projt, C_DIM, C_DIM);
    transpose_kernel<<<dim3(FF_DIM / 32, C_DIM / 32),  256>>>(mlp_w1, mlp1t, C_DIM, FF_DIM);
    transpose_kernel<<<dim3(C_DIM / 32, FF_DIM / 32),  256>>>(mlp_w2, mlp2t, FF_DIM, C_DIM);

    // 1. h1 = bf16(arsinh_norm(h; n1))
    arsinh_norm_kernel<<<(nElem + 255) / 256, 256>>>(h, n1_w, n1_b, h1, nElem);

    // 2. qkv = h1 @ qkv_w + qkv_b   (fp32 out)
    gemm_bf16_kernel<false, false, false><<<dim3(QKV_DIM / BN, M / BM), 256, GEMM_SMEM>>>(
        h1, qkvt, qkv_b, nullptr, qkv, M, QKV_DIM, C_DIM);

    // 3. NATTEN attention (bf16 out)
    natten_kernel<<<(TOKENS * NHEADS) / 8, 256>>>(qkv, attn);

    // 4. hmid = h + attn @ proj_w + proj_b   (fp32 out)
    gemm_bf16_kernel<false, true, false><<<dim3(C_DIM / BN, M / BM), 256, GEMM_SMEM>>>(
        attn, projt, proj_b, h, hmid, M, C_DIM, C_DIM);

    // 5. h2 = bf16(arsinh_norm(hmid; n2))   (reuse g_h1)
    arsinh_norm_kernel<<<(nElem + 255) / 256, 256>>>(hmid, n2_w, n2_b, h1, nElem);

    // 6. ff = bf16(gelu(h2 @ mlp_w1 + mlp_b1))
    gemm_bf16_kernel<true, false, true><<<dim3(FF_DIM / BN, M / BM), 256, GEMM_SMEM>>>(
        h1, mlp1t, mlp_b1, nullptr, ff, M, FF_DIM, C_DIM);

    // 7. out = hmid + ff @ mlp_w2 + mlp_b2   (fp32 out)
    gemm_bf16_kernel<false, true, false><<<dim3(C_DIM / BN, M / BM), 256, GEMM_SMEM>>>(
        ff, mlp2t, mlp_b2, hmid, out, M, C_DIM, FF_DIM);
}

// round 9
// speedup vs baseline: 4.8650x; 1.3236x over previous
#include <cuda_runtime.h>
#include <cuda_bf16.h>
#include <cstdint>

// ---------------------------------------------------------------------------
// LocalAttentionBlock on GB300 (base sm_103 target): bf16 mma.sync m16n8k16
// GEMMs with ldmatrix + warp-per-token NATTEN, norm2 fused into proj epilogue.
// B=16, H=W=64, C=256, heads=8, hd=32
// ---------------------------------------------------------------------------

#define TOKENS   65536
#define C_DIM    256
#define QKV_DIM  768
#define FF_DIM   512
#define NHEADS   8
#define HDIM     32

// Scratch (device globals — allocation-free rule)
__device__ __nv_bfloat16 g_h1  [(size_t)TOKENS * C_DIM];   // h1, then h2
__device__ __nv_bfloat16 g_qkv [(size_t)TOKENS * QKV_DIM];
__device__ __nv_bfloat16 g_attn[(size_t)TOKENS * C_DIM];
__device__ float         g_hmid[(size_t)TOKENS * C_DIM];
__device__ __nv_bfloat16 g_ff  [(size_t)TOKENS * FF_DIM];
// Transposed ([N,K] K-major, bf16) weights
__device__ __nv_bfloat16 g_qkvt [(size_t)QKV_DIM * C_DIM];
__device__ __nv_bfloat16 g_projt[(size_t)C_DIM * C_DIM];
__device__ __nv_bfloat16 g_mlp1t[(size_t)FF_DIM * C_DIM];
__device__ __nv_bfloat16 g_mlp2t[(size_t)C_DIM * FF_DIM];

// ---------------------------------------------------------------------------
// Helpers
// ---------------------------------------------------------------------------
__device__ __forceinline__ uint32_t smem_u32(const void* p) {
    uint32_t a;
    asm("{ .reg .u64 t; cvta.to.shared.u64 t, %1; cvt.u32.u64 %0, t; }"
        : "=r"(a) : "l"(p));
    return a;
}
#define CP_ASYNC16(dst, src) \
    asm volatile("cp.async.cg.shared.global [%0], [%1], 16;" :: "r"(dst), "l"(src))
#define CP_COMMIT() asm volatile("cp.async.commit_group;" ::: "memory")
#define CP_WAIT0()  asm volatile("cp.async.wait_group 0;" ::: "memory")

#define LDSM_X4(r0, r1, r2, r3, addr) \
    asm volatile("ldmatrix.sync.aligned.m8n8.x4.shared.b16 {%0,%1,%2,%3}, [%4];" \
        : "=r"(r0), "=r"(r1), "=r"(r2), "=r"(r3) : "r"(addr))

#define MMA_BF16(cf, av, bv) \
    asm volatile("mma.sync.aligned.m16n8k16.row.col.f32.bf16.bf16.f32 " \
        "{%0,%1,%2,%3}, {%4,%5,%6,%7}, {%8,%9}, {%0,%1,%2,%3};" \
        : "+f"((cf)[0]), "+f"((cf)[1]), "+f"((cf)[2]), "+f"((cf)[3]) \
        : "r"((av)[0]), "r"((av)[1]), "r"((av)[2]), "r"((av)[3]), \
          "r"((bv)[0]), "r"((bv)[1]))

__device__ __forceinline__ float gelu_exact(float v) {
    return 0.5f * v * (1.0f + erff(v * 0.70710678118654752440f));
}

// ---------------------------------------------------------------------------
// Elementwise arsinh norm: y = bf16(w[c]*asinh(x)+b[c])
// ---------------------------------------------------------------------------
__global__ void __launch_bounds__(256) arsinh_norm_kernel(
    const float* __restrict__ x, const float* __restrict__ w,
    const float* __restrict__ b, __nv_bfloat16* __restrict__ y, int n)
{
    int idx = blockIdx.x * 256 + threadIdx.x;
    if (idx < n) {
        int c = idx & (C_DIM - 1);
        y[idx] = __float2bfloat16_rn(fmaf(w[c], asinhf(x[idx]), b[c]));
    }
}

// ---------------------------------------------------------------------------
// Batched transpose of all 4 weights: W[K,N] -> Wt[N,K] bf16. 512 blocks.
// ---------------------------------------------------------------------------
__global__ void __launch_bounds__(256) transpose_all_kernel(
    const float* __restrict__ w0, const float* __restrict__ w1,
    const float* __restrict__ w2, const float* __restrict__ w3,
    __nv_bfloat16* __restrict__ o0, __nv_bfloat16* __restrict__ o1,
    __nv_bfloat16* __restrict__ o2, __nv_bfloat16* __restrict__ o3)
{
    __shared__ float t[32][33];
    int id = blockIdx.x;
    const float* in; __nv_bfloat16* out; int K, N, bx, by;
    if (id < 192)      { in = w0; out = o0; K = 256; N = 768; bx = id % 24;          by = id / 24; }
    else if (id < 256) { in = w1; out = o1; K = 256; N = 256; bx = (id - 192) % 8;   by = (id - 192) / 8; }
    else if (id < 384) { in = w2; out = o2; K = 256; N = 512; bx = (id - 256) % 16;  by = (id - 256) / 16; }
    else               { in = w3; out = o3; K = 512; N = 256; bx = (id - 384) % 8;   by = (id - 384) / 8; }
    int n0 = bx * 32, k0 = by * 32;
    int tx = threadIdx.x & 31, ty = threadIdx.x >> 5;  // 32 x 8
    #pragma unroll
    for (int i = 0; i < 4; i++)
        t[ty + i * 8][tx] = in[(size_t)(k0 + ty + i * 8) * N + n0 + tx];
    __syncthreads();
    #pragma unroll
    for (int i = 0; i < 4; i++)
        out[(size_t)(n0 + ty + i * 8) * K + k0 + tx] =
            __float2bfloat16_rn(t[tx][ty + i * 8]);
}

// ---------------------------------------------------------------------------
// bf16 mma.sync GEMM: C[M,N] = A[M,K] @ Bt[N,K]^T + bias (+gelu)(+res)
// Optional fused norm2: also writes h2 = bf16(n2w*asinh(C)+n2b).
// CTA 128x128, BK=64 (128B rows, XOR-swizzled), double-buffered cp.async,
// ldmatrix.x4 fragments, 8 warps x (32m x 64n).
// ---------------------------------------------------------------------------
#define BM 128
#define BN 128
#define BKE 64
#define STG (BM * BKE * 2)            // 16 KB per tile

template<bool GELU, bool RES, bool OUTBF16, bool NORM2>
__global__ void __launch_bounds__(256, 2)
gemm_bf16_kernel(const __nv_bfloat16* __restrict__ A,
                 const __nv_bfloat16* __restrict__ Bt,
                 const float* __restrict__ bias, const float* __restrict__ res,
                 void* __restrict__ Cout,
                 const float* __restrict__ n2w, const float* __restrict__ n2b,
                 __nv_bfloat16* __restrict__ h2out,
                 int M, int N, int K)
{
    extern __shared__ char smp[];     // [2]A + [2]B = 64 KB
    const uint32_t as_base = smem_u32(smp);
    const uint32_t bs_base = as_base + 2 * STG;

    const int tid  = threadIdx.x;
    const int wid  = tid >> 5;
    const int lane = tid & 31;
    const int g    = lane >> 2;
    const int tig  = lane & 3;
    const int wm   = wid >> 1;
    const int wn   = wid & 1;
    const int bm   = blockIdx.y * BM;
    const int bn   = blockIdx.x * BN;

    const int ar  = (lane & 7) + ((lane >> 3) & 1) * 8;
    const int acb = lane >> 4;
    const int br  = (lane & 7) + ((lane >> 4) & 1) * 8;
    const int bcb = (lane >> 3) & 1;

    float c[2][8][4];
    #pragma unroll
    for (int mt = 0; mt < 2; mt++)
        #pragma unroll
        for (int nt = 0; nt < 8; nt++)
            #pragma unroll
            for (int u = 0; u < 4; u++) c[mt][nt][u] = 0.0f;

    auto load_stage = [&](int buf, int k0) {
        const uint32_t ab = as_base + buf * STG;
        const uint32_t bb = bs_base + buf * STG;
        #pragma unroll
        for (int i = 0; i < 4; i++) {
            const int id = tid + i * 256;
            const int r = id >> 3, ch = id & 7;
            const uint32_t off = (uint32_t)(r * 128 + ((ch ^ (r & 7)) << 4));
            CP_ASYNC16(ab + off, A  + (size_t)(bm + r) * K + k0 + ch * 8);
            CP_ASYNC16(bb + off, Bt + (size_t)(bn + r) * K + k0 + ch * 8);
        }
    };

    load_stage(0, 0);
    CP_COMMIT();

    const int S = K / BKE;
    for (int s = 0; s < S; s++) {
        CP_WAIT0();
        __syncthreads();
        if (s + 1 < S) { load_stage((s + 1) & 1, (s + 1) * BKE); CP_COMMIT(); }

        const uint32_t ab = as_base + (s & 1) * STG;
        const uint32_t bb = bs_base + (s & 1) * STG;

        #pragma unroll
        for (int kk = 0; kk < 4; kk++) {
            uint32_t a[2][4], b[8][2];
            #pragma unroll
            for (int mt = 0; mt < 2; mt++) {
                const int row = wm * 32 + mt * 16 + ar;
                const uint32_t ad = ab + row * 128
                    + (((2 * kk + acb) ^ (row & 7)) << 4);
                LDSM_X4(a[mt][0], a[mt][1], a[mt][2], a[mt][3], ad);
            }
            #pragma unroll
            for (int p = 0; p < 4; p++) {
                const int row = wn * 64 + p * 16 + br;
                const uint32_t bd = bb + row * 128
                    + (((2 * kk + bcb) ^ (row & 7)) << 4);
                LDSM_X4(b[2 * p][0], b[2 * p][1], b[2 * p + 1][0], b[2 * p + 1][1], bd);
            }
            #pragma unroll
            for (int mt = 0; mt < 2; mt++)
                #pragma unroll
                for (int nt = 0; nt < 8; nt++)
                    MMA_BF16(c[mt][nt], a[mt], b[nt]);
        }
        __syncthreads();
    }

    // Epilogue
    #pragma unroll
    for (int mt = 0; mt < 2; mt++) {
        #pragma unroll
        for (int half = 0; half < 2; half++) {
            const int row = bm + wm * 32 + mt * 16 + g + half * 8;
            #pragma unroll
            for (int nt = 0; nt < 8; nt++) {
                const int col = bn + wn * 64 + nt * 8 + tig * 2;
                float v0 = c[mt][nt][half * 2 + 0] + bias[col];
                float v1 = c[mt][nt][half * 2 + 1] + bias[col + 1];
                if (GELU) { v0 = gelu_exact(v0); v1 = gelu_exact(v1); }
                if (RES) {
                    float2 r = *(const float2*)(res + (size_t)row * N + col);
                    v0 += r.x; v1 += r.y;
                }
                if (OUTBF16) {
                    *(__nv_bfloat162*)((__nv_bfloat16*)Cout + (size_t)row * N + col)
                        = __floats2bfloat162_rn(v0, v1);
                } else {
                    *(float2*)((float*)Cout + (size_t)row * N + col)
                        = make_float2(v0, v1);
                }
                if (NORM2) {
                    float h0 = fmaf(n2w[col],     asinhf(v0), n2b[col]);
                    float h1v = fmaf(n2w[col + 1], asinhf(v1), n2b[col + 1]);
                    *(__nv_bfloat162*)(h2out + (size_t)row * N + col)
                        = __floats2bfloat162_rn(h0, h1v);
                }
            }
        }
    }
}

// ---------------------------------------------------------------------------
// NATTEN 3x3: ONE warp per token, all 8 heads. Lane owns 8 contiguous
// channels; each head = one 4-lane group (2-shfl dot reduction).
// qkv bf16: per-token row [q(256) | k(256) | v(256)].
// ---------------------------------------------------------------------------
__global__ void __launch_bounds__(256) natten_kernel(
    const __nv_bfloat16* __restrict__ qkv, __nv_bfloat16* __restrict__ out)
{
    const int token = (blockIdx.x * 256 + threadIdx.x) >> 5;
    const int lane  = threadIdx.x & 31;
    const int c0    = lane * 8;
    const int b = token >> 12;
    const int i = (token >> 6) & 63;
    const int j = token & 63;

    const float scale = 0.17677669529663687f;  // 1/sqrt(32)

    // Load q (8 channels), pre-scaled
    float q[8];
    {
        uint4 qp = *(const uint4*)(qkv + (size_t)token * QKV_DIM + c0);
        const uint32_t* qu = (const uint32_t*)&qp;
        #pragma unroll
        for (int u = 0; u < 4; u++) {
            float2 f = __bfloat1622float2(*(const __nv_bfloat162*)&qu[u]);
            q[2 * u]     = f.x * scale;
            q[2 * u + 1] = f.y * scale;
        }
    }

    const int ri = min(max(i - 1, 0), 61);
    const int ci = min(max(j - 1, 0), 61);

    uint4 vv[9];
    float s[9];
    #pragma unroll
    for (int m = 0; m < 9; m++) {
        const int ni = ri + m / 3;
        const int nj = ci + m % 3;
        const __nv_bfloat16* nb = qkv + ((size_t)((b << 6) + ni) * 64 + nj) * QKV_DIM;
        uint4 kp = *(const uint4*)(nb + 256 + c0);
        vv[m]    = *(const uint4*)(nb + 512 + c0);
        const uint32_t* ku = (const uint32_t*)&kp;
        float dot = 0.0f;
        #pragma unroll
        for (int u = 0; u < 4; u++) {
            float2 f = __bfloat1622float2(*(const __nv_bfloat162*)&ku[u]);
            dot = fmaf(q[2 * u], f.x, dot);
            dot = fmaf(q[2 * u + 1], f.y, dot);
        }
        dot += __shfl_xor_sync(0xffffffffu, dot, 1);
        dot += __shfl_xor_sync(0xffffffffu, dot, 2);
        s[m] = dot;   // all 4 lanes of the head group hold the score
    }

    float mx = s[0];
    #pragma unroll
    for (int m = 1; m < 9; m++) mx = fmaxf(mx, s[m]);
    float sum = 0.0f;
    #pragma unroll
    for (int m = 0; m < 9; m++) { s[m] = __expf(s[m] - mx); sum += s[m]; }
    const float inv = 1.0f / sum;

    float o[8];
    #pragma unroll
    for (int u = 0; u < 8; u++) o[u] = 0.0f;
    #pragma unroll
    for (int m = 0; m < 9; m++) {
        const uint32_t* vu = (const uint32_t*)&vv[m];
        #pragma unroll
        for (int u = 0; u < 4; u++) {
            float2 f = __bfloat1622float2(*(const __nv_bfloat162*)&vu[u]);
            o[2 * u]     = fmaf(s[m], f.x, o[2 * u]);
            o[2 * u + 1] = fmaf(s[m], f.y, o[2 * u + 1]);
        }
    }

    uint4 op;
    uint32_t* ou = (uint32_t*)&op;
    #pragma unroll
    for (int u = 0; u < 4; u++) {
        __nv_bfloat162 p = __floats2bfloat162_rn(o[2 * u] * inv, o[2 * u + 1] * inv);
        ou[u] = *(const uint32_t*)&p;
    }
    *(uint4*)(out + (size_t)token * C_DIM + c0) = op;
}

// ---------------------------------------------------------------------------
// Launcher
// ---------------------------------------------------------------------------
#define GEMM_SMEM (4 * STG)   // 64 KB

extern "C" void kernel_launch(void* const* d_in, const int* in_sizes, int n_in,
                              void* d_out, int out_size)
{
    (void)in_sizes; (void)n_in; (void)out_size;
    const float* h      = (const float*)d_in[0];
    const float* qkv_w  = (const float*)d_in[1];
    const float* qkv_b  = (const float*)d_in[2];
    const float* proj_w = (const float*)d_in[3];
    const float* proj_b = (const float*)d_in[4];
    const float* n1_w   = (const float*)d_in[5];
    const float* n1_b   = (const float*)d_in[6];
    const float* n2_w   = (const float*)d_in[7];
    const float* n2_b   = (const float*)d_in[8];
    const float* mlp_w1 = (const float*)d_in[9];
    const float* mlp_b1 = (const float*)d_in[10];
    const float* mlp_w2 = (const float*)d_in[11];
    const float* mlp_b2 = (const float*)d_in[12];
    float* out = (float*)d_out;

    __nv_bfloat16 *h1, *qkv, *attn, *ff, *qkvt, *projt, *mlp1t, *mlp2t;
    float *hmid;
    cudaGetSymbolAddress((void**)&h1,    g_h1);
    cudaGetSymbolAddress((void**)&qkv,   g_qkv);
    cudaGetSymbolAddress((void**)&attn,  g_attn);
    cudaGetSymbolAddress((void**)&hmid,  g_hmid);
    cudaGetSymbolAddress((void**)&ff,    g_ff);
    cudaGetSymbolAddress((void**)&qkvt,  g_qkvt);
    cudaGetSymbolAddress((void**)&projt, g_projt);
    cudaGetSymbolAddress((void**)&mlp1t, g_mlp1t);
    cudaGetSymbolAddress((void**)&mlp2t, g_mlp2t);

    cudaFuncSetAttribute(gemm_bf16_kernel<false, false, true,  false>,
                         cudaFuncAttributeMaxDynamicSharedMemorySize, GEMM_SMEM);
    cudaFuncSetAttribute(gemm_bf16_kernel<false, true,  false, true>,
                         cudaFuncAttributeMaxDynamicSharedMemorySize, GEMM_SMEM);
    cudaFuncSetAttribute(gemm_bf16_kernel<true,  false, true,  false>,
                         cudaFuncAttributeMaxDynamicSharedMemorySize, GEMM_SMEM);
    cudaFuncSetAttribute(gemm_bf16_kernel<false, true,  false, false>,
                         cudaFuncAttributeMaxDynamicSharedMemorySize, GEMM_SMEM);

    const int M = TOKENS;
    const int nElem = TOKENS * C_DIM;

    // Weight transposes (bf16), one launch
    transpose_all_kernel<<<512, 256>>>(qkv_w, proj_w, mlp_w1, mlp_w2,
                                       qkvt, projt, mlp1t, mlp2t);

    // 1. h1 = bf16(arsinh_norm(h; n1))
    arsinh_norm_kernel<<<(nElem + 255) / 256, 256>>>(h, n1_w, n1_b, h1, nElem);

    // 2. qkv = h1 @ qkv_w + qkv_b   (bf16 out)
    gemm_bf16_kernel<false, false, true, false>
        <<<dim3(QKV_DIM / BN, M / BM), 256, GEMM_SMEM>>>(
        h1, qkvt, qkv_b, nullptr, qkv, nullptr, nullptr, nullptr,
        M, QKV_DIM, C_DIM);

    // 3. NATTEN attention (bf16 in/out), 1 warp per token
    natten_kernel<<<TOKENS / 8, 256>>>(qkv, attn);

    // 4. hmid = h + attn @ proj_w + proj_b  (fp32) ; fused h2 = norm2(hmid) bf16
    gemm_bf16_kernel<false, true, false, true>
        <<<dim3(C_DIM / BN, M / BM), 256, GEMM_SMEM>>>(
        attn, projt, proj_b, h, hmid, n2_w, n2_b, h1,
        M, C_DIM, C_DIM);

    // 5. ff = bf16(gelu(h2 @ mlp_w1 + mlp_b1))
    gemm_bf16_kernel<true, false, true, false>
        <<<dim3(FF_DIM / BN, M / BM), 256, GEMM_SMEM>>>(
        h1, mlp1t, mlp_b1, nullptr, ff, nullptr, nullptr, nullptr,
        M, FF_DIM, C_DIM);

    // 6. out = hmid + ff @ mlp_w2 + mlp_b2  (fp32)
    gemm_bf16_kernel<false, true, false, false>
        <<<dim3(C_DIM / BN, M / BM), 256, GEMM_SMEM>>>(
        ff, mlp2t, mlp_b2, hmid, out, nullptr, nullptr, nullptr,
        M, C_DIM, FF_DIM);
}